// round 5
// baseline (speedup 1.0000x reference)
#include <cuda_runtime.h>
#include <cstdint>

#define NFACES 1000
#define NPAD   1024
#define IMG    256
#define SPLIT  16
#define CHUNK  64                 // 16*64 = 1024 faces padded
#define CULL_T 25.5f              // frag < 2^-25.5 -> (1-frag) rounds to exactly 1.0f

__device__ float4   g_c0[NPAD];               // (A0,B0,C0,A1)
__device__ float4   g_c1[NPAD];               // (B1,C1,A2,B2)
__device__ float    g_c2[NPAD];               // C2
__device__ int      g_degblk[4];              // degenerate counts per prep block
__device__ float    g_part[SPLIT * IMG * IMG];
__device__ unsigned g_mask[256];              // per-tile plane bitmask (prep zeroes)
__device__ float    g_row[256];
__device__ unsigned g_tcnt[256];              // wrapping -> replay-safe
__device__ unsigned g_done;                   // wrapping -> replay-safe

__device__ __forceinline__ float ex2f(float x) {
    float y; asm("ex2.approx.f32 %0, %1;" : "=f"(y) : "f"(x)); return y;
}
__device__ __forceinline__ float rcpaf(float x) {
    float y; asm("rcp.approx.f32 %0, %1;" : "=f"(y) : "f"(x)); return y;
}
__device__ __forceinline__ float rsqaf(float x) {
    float y; asm("rsqrt.approx.f32 %0, %1;" : "=f"(y) : "f"(x)); return y;
}

// ---------------------------------------------------------------------------
// Kernel 1: per-face prep -> packed edge coefficients + degenerate counts.
// Also resets g_mask (block 0). 4 blocks x 256 threads.
// ---------------------------------------------------------------------------
__global__ void __launch_bounds__(256) prep_kernel(
    const float* __restrict__ verts,
    const int*   __restrict__ faces,
    const float* __restrict__ cam)
{
    __shared__ int wdeg[8];
    const int tid = threadIdx.x;
    const int f   = blockIdx.x * 256 + tid;

    if (blockIdx.x == 0) g_mask[tid] = 0u;   // replay reset (prep precedes render)

    bool deg = false;

    if (f < NFACES) {
        float ex = cam[0], ey = cam[1], ez = cam[2];

        // camera basis (z = normalize(-eye), up = (0,1,0))
        float rz = rsqaf(ex*ex + ey*ey + ez*ez);
        float zx = -ex * rz, zy = -ey * rz, zz = -ez * rz;
        float rx = rsqaf(zz*zz + zx*zx);
        float xx = zz * rx, xz = -zx * rx;
        float yx = zy * xz;
        float yy = zz * xx - zx * xz;
        float yz = -zy * xx;

        const float w = 0.57735026918962576f;  // tan(30 deg)

        float px[3], py[3];
        #pragma unroll
        for (int k = 0; k < 3; k++) {
            int vi = faces[3 * f + k];
            float dx = verts[3 * vi + 0] - ex;
            float dy = verts[3 * vi + 1] - ey;
            float dz = verts[3 * vi + 2] - ez;
            float cx = xx * dx + xz * dz;            // x.y == 0
            float cy = yx * dx + yy * dy + yz * dz;
            float cz = zx * dx + zy * dy + zz * dz;
            float rzw = rcpaf(cz * w);
            px[k] = cx * rzw;
            py[k] = cy * rzw;
        }

        float e01x = px[1] - px[0], e01y = py[1] - py[0];
        float e02x = px[2] - px[0], e02y = py[2] - py[0];
        float area = __fmul_rn(e01x, e02y) - __fmul_rn(e01y, e02x);

        if (area == 0.f) {
            deg = true;   // duplicate-vertex face: frag = 0.125 everywhere (analytic)
            g_c0[f] = make_float4(0.f, 0.f, 1e9f, 0.f);  // q huge -> always culled
            g_c1[f] = make_float4(0.f, 0.f, 0.f, 0.f);
            g_c2[f] = 0.f;
        } else {
            float s = (area > 0.f) ? 1.f : -1.f;
            float K = s * 144.26950408889634f;  // inv_sigma * log2(e)

            float A[3], B[3], C[3];
            const int ia[3] = {0, 1, 2}, ib[3] = {1, 2, 0};
            #pragma unroll
            for (int e = 0; e < 3; e++) {
                float ax = px[ib[e]] - px[ia[e]];
                float ay = py[ib[e]] - py[ia[e]];
                float rlen = rsqaf(ax*ax + ay*ay);
                float nx = -ay * rlen, ny = ax * rlen;
                A[e] = -K * nx;
                B[e] = -K * ny;
                C[e] =  K * (px[ia[e]] * nx + py[ia[e]] * ny);
            }
            g_c0[f] = make_float4(A[0], B[0], C[0], A[1]);
            g_c1[f] = make_float4(B[1], C[1], A[2], B[2]);
            g_c2[f] = C[2];
        }
    } else {
        // padded faces: always culled
        g_c0[f] = make_float4(0.f, 0.f, 1e9f, 0.f);
        g_c1[f] = make_float4(0.f, 0.f, 0.f, 0.f);
        g_c2[f] = 0.f;
    }

    unsigned bal = __ballot_sync(0xffffffffu, deg);
    if ((tid & 31) == 0) wdeg[tid >> 5] = __popc(bal);
    __syncthreads();
    if (tid == 0) {
        int nd = 0;
        #pragma unroll
        for (int i = 0; i < 8; i++) nd += wdeg[i];
        g_degblk[blockIdx.x] = nd;
    }
}

// ---------------------------------------------------------------------------
// Kernel 2: fused render + combine + reduce. grid (16,16,SPLIT), 256 threads.
// ---------------------------------------------------------------------------
__global__ void __launch_bounds__(256) render_kernel(
    const float* __restrict__ ref,
    float*       __restrict__ out)
{
    __shared__ float4 sA[CHUNK], sB[CHUNK];
    __shared__ float  sC[CHUNK];
    __shared__ int    wcnt[2];
    __shared__ int    s_flag;
    __shared__ unsigned s_mask;
    __shared__ float  red[256];

    const int tid  = threadIdx.x;
    const int lane = tid & 31, wid = tid >> 5;
    const int c0 = blockIdx.x * 16, r0 = blockIdx.y * 16;
    const int tileIdx = blockIdx.y * 16 + blockIdx.x;
    const int z = blockIdx.z;

    const float xmin = (2.f * c0 + 1.f)        * (1.f / 256.f) - 1.f;
    const float xmax = (2.f * (c0 + 15) + 1.f) * (1.f / 256.f) - 1.f;
    const float ymax = 1.f - (2.f * r0 + 1.f)        * (1.f / 256.f);
    const float ymin = 1.f - (2.f * (r0 + 15) + 1.f) * (1.f / 256.f);

    // ---------------- Phase A: load coeffs + sum-relu tile cull -------------
    bool keep = false;
    float4 fa = make_float4(0,0,0,0), fb = make_float4(0,0,0,0);
    float  fcc = 0.f;
    if (tid < CHUNK) {
        int f = z * CHUNK + tid;
        fa = g_c0[f]; fb = g_c1[f]; fcc = g_c2[f];
        float m0 = (fa.x > 0.f ? fa.x * xmin : fa.x * xmax)
                 + (fa.y > 0.f ? fa.y * ymin : fa.y * ymax) + fa.z;
        float m1 = (fa.w > 0.f ? fa.w * xmin : fa.w * xmax)
                 + (fb.x > 0.f ? fb.x * ymin : fb.x * ymax) + fb.y;
        float m2 = (fb.z > 0.f ? fb.z * xmin : fb.z * xmax)
                 + (fb.w > 0.f ? fb.w * ymin : fb.w * ymax) + fcc;
        float q = fmaxf(m0, 0.f) + fmaxf(m1, 0.f) + fmaxf(m2, 0.f);
        keep = q < CULL_T;
    }
    unsigned balK = __ballot_sync(0xffffffffu, keep);
    if (lane == 0 && wid < 2) wcnt[wid] = __popc(balK);
    __syncthreads();

    const int cnt = wcnt[0] + wcnt[1];
    if (keep) {
        int off = __popc(balK & ((1u << lane) - 1u)) + (wid == 1 ? wcnt[0] : 0);
        sA[off] = fa; sB[off] = fb; sC[off] = fcc;
    }
    __syncthreads();

    const int gc = c0 + (tid & 15);
    const int gr = r0 + (tid >> 4);
    const int pix = gr * IMG + gc;

    // ---------------- Phase B: per-pixel partial product ---------------------
    if (cnt > 0) {
        const float X = (2.f * gc + 1.f) * (1.f / 256.f) - 1.f;
        const float Y = 1.f - (2.f * gr + 1.f) * (1.f / 256.f);
        float prod = 1.f;
        for (int i = 0; i < cnt; i++) {
            float4 a = sA[i];
            float4 b = sB[i];
            float  cc = sC[i];
            float L0 = fmaf(a.x, X, fmaf(a.y, Y, a.z));
            float L1 = fmaf(a.w, X, fmaf(b.x, Y, b.y));
            float L2 = fmaf(b.z, X, fmaf(b.w, Y, cc));
            float q = fmaxf(L0, 0.f) + fmaxf(L1, 0.f) + fmaxf(L2, 0.f);
            if (__all_sync(0xffffffffu, q >= CULL_T)) continue;  // frag rounds to 0
            float u0 = 1.f + ex2f(L0);
            float u1 = 1.f + ex2f(L1);
            float u2 = 1.f + ex2f(L2);
            float r  = rcpaf(u0 * u1 * u2);   // = frag (exactly 1.0 deep inside)
            prod = fmaf(prod, -r, prod);      // prod *= (1 - frag)
            // opaque-covered: prod==0 is absorbing -> whole warp can stop
            if (__all_sync(0xffffffffu, prod == 0.f)) break;
        }
        g_part[z * (IMG * IMG) + pix] = prod;
    }

    // ---------------- Phase C: last chunk per tile combines ------------------
    __threadfence();
    if (tid == 0) {
        if (cnt > 0) atomicOr(&g_mask[tileIdx], 1u << z);
        unsigned old = atomicInc(&g_tcnt[tileIdx], SPLIT - 1);  // wraps -> replay-safe
        s_flag = (old == SPLIT - 1);
        if (s_flag) s_mask = atomicOr(&g_mask[tileIdx], 0u);
    }
    __syncthreads();
    if (!s_flag) return;

    __threadfence();  // acquire: planes from other blocks visible
    unsigned mask = s_mask;
    float p = 1.f;
    while (mask) {
        int zz = __ffs(mask) - 1;
        mask &= mask - 1;
        p *= g_part[zz * (IMG * IMG) + pix];
    }
    // degenerate faces: uniform frag 0.125 -> global factor 0.875^ndeg
    int nd = g_degblk[0] + g_degblk[1] + g_degblk[2] + g_degblk[3];
    for (int i = 0; i < nd; i++) p *= 0.875f;

    float sil = 1.f - p;
    float d = sil - ref[pix];
    red[tid] = d * d;
    __syncthreads();
    #pragma unroll
    for (int s2 = 128; s2 > 0; s2 >>= 1) {
        if (tid < s2) red[tid] += red[tid + s2];
        __syncthreads();
    }

    // ---------------- Phase D: last tile sums 256 tile losses ----------------
    if (tid == 0) {
        g_row[tileIdx] = red[0];
        __threadfence();
        unsigned old = atomicInc(&g_done, 255u);  // wraps each replay
        s_flag = (old == 255u);
    }
    __syncthreads();
    if (!s_flag) return;

    __threadfence();
    red[tid] = g_row[tid];
    __syncthreads();
    #pragma unroll
    for (int s2 = 128; s2 > 0; s2 >>= 1) {
        if (tid < s2) red[tid] += red[tid + s2];
        __syncthreads();
    }
    if (tid == 0) out[0] = red[0];
}

extern "C" void kernel_launch(void* const* d_in, const int* in_sizes, int n_in,
                              void* d_out, int out_size)
{
    const float* verts = (const float*)d_in[0];   // (1,502,3)
    const int*   faces = (const int*)  d_in[1];   // (1,1000,3)
    const float* cam   = (const float*)d_in[2];   // (3,)
    const float* ref   = (const float*)d_in[3];   // (1,256,256)

    prep_kernel<<<4, 256>>>(verts, faces, cam);

    dim3 grid(IMG / 16, IMG / 16, SPLIT);
    render_kernel<<<grid, 256>>>(ref, (float*)d_out);
}

// round 6
// speedup vs baseline: 1.1266x; 1.1266x over previous
#include <cuda_runtime.h>
#include <cstdint>

#define NFACES 1000
#define NPAD   1024
#define IMG    256
#define SPLIT  8
#define CHUNK  128                // 8*128 = 1024 faces padded
#define CULL_T 25.5f              // frag < 2^-25.5 -> (1-frag) rounds to exactly 1.0f

__device__ float4   g_c0[NPAD];               // (A0,B0,C0,A1)
__device__ float4   g_c1[NPAD];               // (B1,C1,A2,B2)
__device__ float    g_c2[NPAD];               // C2
__device__ int      g_degblk[4];              // degenerate counts per prep block
__device__ float    g_part[SPLIT * IMG * IMG];
__device__ float    g_row[256];
__device__ unsigned g_tcnt[256];              // wrapping -> replay-safe
__device__ unsigned g_done;                   // wrapping -> replay-safe

__device__ __forceinline__ float ex2f(float x) {
    float y; asm("ex2.approx.f32 %0, %1;" : "=f"(y) : "f"(x)); return y;
}
__device__ __forceinline__ float rcpaf(float x) {
    float y; asm("rcp.approx.f32 %0, %1;" : "=f"(y) : "f"(x)); return y;
}
__device__ __forceinline__ float rsqaf(float x) {
    float y; asm("rsqrt.approx.f32 %0, %1;" : "=f"(y) : "f"(x)); return y;
}

// ---------------------------------------------------------------------------
// Kernel 1: per-face prep -> packed edge coefficients + degenerate counts.
// ---------------------------------------------------------------------------
__global__ void __launch_bounds__(256) prep_kernel(
    const float* __restrict__ verts,
    const int*   __restrict__ faces,
    const float* __restrict__ cam)
{
    __shared__ int wdeg[8];
    const int tid = threadIdx.x;
    const int f   = blockIdx.x * 256 + tid;

    bool deg = false;

    if (f < NFACES) {
        float ex = cam[0], ey = cam[1], ez = cam[2];

        // camera basis (z = normalize(-eye), up = (0,1,0))
        float rz = rsqaf(ex*ex + ey*ey + ez*ez);
        float zx = -ex * rz, zy = -ey * rz, zz = -ez * rz;
        float rx = rsqaf(zz*zz + zx*zx);
        float xx = zz * rx, xz = -zx * rx;
        float yx = zy * xz;
        float yy = zz * xx - zx * xz;
        float yz = -zy * xx;

        const float w = 0.57735026918962576f;  // tan(30 deg)

        float px[3], py[3];
        #pragma unroll
        for (int k = 0; k < 3; k++) {
            int vi = faces[3 * f + k];
            float dx = verts[3 * vi + 0] - ex;
            float dy = verts[3 * vi + 1] - ey;
            float dz = verts[3 * vi + 2] - ez;
            float cx = xx * dx + xz * dz;            // x.y == 0
            float cy = yx * dx + yy * dy + yz * dz;
            float cz = zx * dx + zy * dy + zz * dz;
            float rzw = rcpaf(cz * w);
            px[k] = cx * rzw;
            py[k] = cy * rzw;
        }

        float e01x = px[1] - px[0], e01y = py[1] - py[0];
        float e02x = px[2] - px[0], e02y = py[2] - py[0];
        float area = __fmul_rn(e01x, e02y) - __fmul_rn(e01y, e02x);

        if (area == 0.f) {
            deg = true;   // duplicate-vertex face: frag = 0.125 everywhere (analytic)
            g_c0[f] = make_float4(0.f, 0.f, 1e9f, 0.f);  // q huge -> always culled
            g_c1[f] = make_float4(0.f, 0.f, 0.f, 0.f);
            g_c2[f] = 0.f;
        } else {
            float s = (area > 0.f) ? 1.f : -1.f;
            float K = s * 144.26950408889634f;  // inv_sigma * log2(e)

            float A[3], B[3], C[3];
            const int ia[3] = {0, 1, 2}, ib[3] = {1, 2, 0};
            #pragma unroll
            for (int e = 0; e < 3; e++) {
                float ax = px[ib[e]] - px[ia[e]];
                float ay = py[ib[e]] - py[ia[e]];
                float rlen = rsqaf(ax*ax + ay*ay);
                float nx = -ay * rlen, ny = ax * rlen;
                A[e] = -K * nx;
                B[e] = -K * ny;
                C[e] =  K * (px[ia[e]] * nx + py[ia[e]] * ny);
            }
            g_c0[f] = make_float4(A[0], B[0], C[0], A[1]);
            g_c1[f] = make_float4(B[1], C[1], A[2], B[2]);
            g_c2[f] = C[2];
        }
    } else {
        g_c0[f] = make_float4(0.f, 0.f, 1e9f, 0.f);   // padded: always culled
        g_c1[f] = make_float4(0.f, 0.f, 0.f, 0.f);
        g_c2[f] = 0.f;
    }

    unsigned bal = __ballot_sync(0xffffffffu, deg);
    if ((tid & 31) == 0) wdeg[tid >> 5] = __popc(bal);
    __syncthreads();
    if (tid == 0) {
        int nd = 0;
        #pragma unroll
        for (int i = 0; i < 8; i++) nd += wdeg[i];
        g_degblk[blockIdx.x] = nd;
    }
}

// ---------------------------------------------------------------------------
// Kernel 2: fused render + combine + reduce. grid (16,16,SPLIT), 256 threads.
// ---------------------------------------------------------------------------
__global__ void __launch_bounds__(256) render_kernel(
    const float* __restrict__ ref,
    float*       __restrict__ out)
{
    __shared__ float4 sA[CHUNK], sB[CHUNK];
    __shared__ float  sC[CHUNK];
    __shared__ int    wcnt[4];
    __shared__ int    s_flag;
    __shared__ float  red[256];

    const int tid  = threadIdx.x;
    const int lane = tid & 31, wid = tid >> 5;
    const int c0 = blockIdx.x * 16, r0 = blockIdx.y * 16;
    const int tileIdx = blockIdx.y * 16 + blockIdx.x;
    const int z = blockIdx.z;

    const float xmin = (2.f * c0 + 1.f)        * (1.f / 256.f) - 1.f;
    const float xmax = (2.f * (c0 + 15) + 1.f) * (1.f / 256.f) - 1.f;
    const float ymax = 1.f - (2.f * r0 + 1.f)        * (1.f / 256.f);
    const float ymin = 1.f - (2.f * (r0 + 15) + 1.f) * (1.f / 256.f);

    // ---------------- Phase A: load coeffs + sum-relu tile cull -------------
    bool keep = false;
    float4 fa = make_float4(0,0,0,0), fb = make_float4(0,0,0,0);
    float  fcc = 0.f;
    if (tid < CHUNK) {
        int f = z * CHUNK + tid;
        fa = g_c0[f]; fb = g_c1[f]; fcc = g_c2[f];
        float m0 = (fa.x > 0.f ? fa.x * xmin : fa.x * xmax)
                 + (fa.y > 0.f ? fa.y * ymin : fa.y * ymax) + fa.z;
        float m1 = (fa.w > 0.f ? fa.w * xmin : fa.w * xmax)
                 + (fb.x > 0.f ? fb.x * ymin : fb.x * ymax) + fb.y;
        float m2 = (fb.z > 0.f ? fb.z * xmin : fb.z * xmax)
                 + (fb.w > 0.f ? fb.w * ymin : fb.w * ymax) + fcc;
        float q = fmaxf(m0, 0.f) + fmaxf(m1, 0.f) + fmaxf(m2, 0.f);
        keep = q < CULL_T;
    }
    unsigned balK = __ballot_sync(0xffffffffu, keep);
    if (lane == 0 && wid < 4) wcnt[wid] = __popc(balK);
    __syncthreads();

    const int cnt = wcnt[0] + wcnt[1] + wcnt[2] + wcnt[3];
    if (keep) {
        int off = __popc(balK & ((1u << lane) - 1u));
        #pragma unroll
        for (int w2 = 0; w2 < 3; w2++) if (w2 < wid) off += wcnt[w2];
        sA[off] = fa; sB[off] = fb; sC[off] = fcc;
    }
    __syncthreads();

    const int gc = c0 + (tid & 15);
    const int gr = r0 + (tid >> 4);
    const int pix = gr * IMG + gc;

    // ---------------- Phase B: per-pixel partial product ---------------------
    float prod = 1.f;
    if (cnt > 0) {
        const float X = (2.f * gc + 1.f) * (1.f / 256.f) - 1.f;
        const float Y = 1.f - (2.f * gr + 1.f) * (1.f / 256.f);
        for (int i = 0; i < cnt; i++) {
            float4 a = sA[i];
            float4 b = sB[i];
            float  cc = sC[i];
            float L0 = fmaf(a.x, X, fmaf(a.y, Y, a.z));
            float L1 = fmaf(a.w, X, fmaf(b.x, Y, b.y));
            float L2 = fmaf(b.z, X, fmaf(b.w, Y, cc));
            float q = fmaxf(L0, 0.f) + fmaxf(L1, 0.f) + fmaxf(L2, 0.f);
            if (__all_sync(0xffffffffu, q >= CULL_T)) continue;  // frag rounds to 0
            float u0 = 1.f + ex2f(L0);
            float u1 = 1.f + ex2f(L1);
            float u2 = 1.f + ex2f(L2);
            float r  = rcpaf(u0 * u1 * u2);   // = frag
            prod = fmaf(prod, -r, prod);      // prod *= (1 - frag)
        }
    }
    g_part[z * (IMG * IMG) + pix] = prod;

    // ---------------- Phase C: last chunk per tile combines ------------------
    __syncthreads();                        // all writes done block-wide
    if (tid == 0) {
        __threadfence();                    // release: publish block's g_part plane
        unsigned old = atomicInc(&g_tcnt[tileIdx], SPLIT - 1);  // wraps -> replay-safe
        s_flag = (old == SPLIT - 1);
        if (s_flag) __threadfence();        // acquire: other planes now visible
    }
    __syncthreads();
    if (!s_flag) return;

    float p = 1.f;
    #pragma unroll
    for (int zz = 0; zz < SPLIT; zz++) p *= g_part[zz * (IMG * IMG) + pix];
    // degenerate faces: uniform frag 0.125 -> global factor 0.875^ndeg
    int nd = g_degblk[0] + g_degblk[1] + g_degblk[2] + g_degblk[3];
    for (int i = 0; i < nd; i++) p *= 0.875f;

    float sil = 1.f - p;
    float d = sil - ref[pix];
    red[tid] = d * d;
    __syncthreads();
    #pragma unroll
    for (int s2 = 128; s2 > 0; s2 >>= 1) {
        if (tid < s2) red[tid] += red[tid + s2];
        __syncthreads();
    }

    // ---------------- Phase D: last tile sums 256 tile losses ----------------
    if (tid == 0) {
        g_row[tileIdx] = red[0];
        __threadfence();                    // release tile loss
        unsigned old = atomicInc(&g_done, 255u);  // wraps each replay
        s_flag = (old == 255u);
        if (s_flag) __threadfence();        // acquire all tile losses
    }
    __syncthreads();
    if (!s_flag) return;

    red[tid] = g_row[tid];
    __syncthreads();
    #pragma unroll
    for (int s2 = 128; s2 > 0; s2 >>= 1) {
        if (tid < s2) red[tid] += red[tid + s2];
        __syncthreads();
    }
    if (tid == 0) out[0] = red[0];
}

extern "C" void kernel_launch(void* const* d_in, const int* in_sizes, int n_in,
                              void* d_out, int out_size)
{
    const float* verts = (const float*)d_in[0];   // (1,502,3)
    const int*   faces = (const int*)  d_in[1];   // (1,1000,3)
    const float* cam   = (const float*)d_in[2];   // (3,)
    const float* ref   = (const float*)d_in[3];   // (1,256,256)

    prep_kernel<<<4, 256>>>(verts, faces, cam);

    dim3 grid(IMG / 16, IMG / 16, SPLIT);
    render_kernel<<<grid, 256>>>(ref, (float*)d_out);
}

// round 7
// speedup vs baseline: 1.2480x; 1.1077x over previous
#include <cuda_runtime.h>
#include <cstdint>

#define NFACES 1000
#define NPAD   1024
#define IMG    256
#define SPLIT  8
#define CHUNK  128                // 8*128 = 1024 faces padded
#define CULL_T 25.5f              // frag < 2^-25.5 -> (1-frag) rounds to exactly 1.0f

__device__ float4   g_c0[NPAD];               // (A0,B0,C0,A1)
__device__ float4   g_c1[NPAD];               // (B1,C1,A2,B2)
__device__ float    g_c2[NPAD];               // C2
__device__ int      g_degblk[4];              // degenerate counts per prep block
__device__ float    g_part[SPLIT * IMG * IMG];
__device__ float    g_row[256];
__device__ unsigned g_tcnt[256];              // wrapping -> replay-safe
__device__ unsigned g_done;                   // wrapping -> replay-safe

__device__ __forceinline__ float ex2f(float x) {
    float y; asm("ex2.approx.f32 %0, %1;" : "=f"(y) : "f"(x)); return y;
}
__device__ __forceinline__ float rcpaf(float x) {
    float y; asm("rcp.approx.f32 %0, %1;" : "=f"(y) : "f"(x)); return y;
}
__device__ __forceinline__ float rsqaf(float x) {
    float y; asm("rsqrt.approx.f32 %0, %1;" : "=f"(y) : "f"(x)); return y;
}

// ---------------------------------------------------------------------------
// Kernel 1: per-face prep -> packed edge coefficients + degenerate counts.
// ---------------------------------------------------------------------------
__global__ void __launch_bounds__(256) prep_kernel(
    const float* __restrict__ verts,
    const int*   __restrict__ faces,
    const float* __restrict__ cam)
{
    __shared__ int wdeg[8];
    const int tid = threadIdx.x;
    const int f   = blockIdx.x * 256 + tid;

    bool deg = false;

    if (f < NFACES) {
        float ex = cam[0], ey = cam[1], ez = cam[2];

        // camera basis (z = normalize(-eye), up = (0,1,0))
        float rz = rsqaf(ex*ex + ey*ey + ez*ez);
        float zx = -ex * rz, zy = -ey * rz, zz = -ez * rz;
        float rx = rsqaf(zz*zz + zx*zx);
        float xx = zz * rx, xz = -zx * rx;
        float yx = zy * xz;
        float yy = zz * xx - zx * xz;
        float yz = -zy * xx;

        const float w = 0.57735026918962576f;  // tan(30 deg)

        float px[3], py[3];
        #pragma unroll
        for (int k = 0; k < 3; k++) {
            int vi = faces[3 * f + k];
            float dx = verts[3 * vi + 0] - ex;
            float dy = verts[3 * vi + 1] - ey;
            float dz = verts[3 * vi + 2] - ez;
            float cx = xx * dx + xz * dz;            // x.y == 0
            float cy = yx * dx + yy * dy + yz * dz;
            float cz = zx * dx + zy * dy + zz * dz;
            float rzw = rcpaf(cz * w);
            px[k] = cx * rzw;
            py[k] = cy * rzw;
        }

        float e01x = px[1] - px[0], e01y = py[1] - py[0];
        float e02x = px[2] - px[0], e02y = py[2] - py[0];
        float area = __fmul_rn(e01x, e02y) - __fmul_rn(e01y, e02x);

        if (area == 0.f) {
            deg = true;   // duplicate-vertex face: frag = 0.125 everywhere (analytic)
            g_c0[f] = make_float4(0.f, 0.f, 1e9f, 0.f);  // inert: always culled / no-op
            g_c1[f] = make_float4(0.f, 0.f, 0.f, 0.f);
            g_c2[f] = 0.f;
        } else {
            float s = (area > 0.f) ? 1.f : -1.f;
            float K = s * 144.26950408889634f;  // inv_sigma * log2(e)

            float A[3], B[3], C[3];
            const int ia[3] = {0, 1, 2}, ib[3] = {1, 2, 0};
            #pragma unroll
            for (int e = 0; e < 3; e++) {
                float ax = px[ib[e]] - px[ia[e]];
                float ay = py[ib[e]] - py[ia[e]];
                float rlen = rsqaf(ax*ax + ay*ay);
                float nx = -ay * rlen, ny = ax * rlen;
                A[e] = -K * nx;
                B[e] = -K * ny;
                C[e] =  K * (px[ia[e]] * nx + py[ia[e]] * ny);
            }
            g_c0[f] = make_float4(A[0], B[0], C[0], A[1]);
            g_c1[f] = make_float4(B[1], C[1], A[2], B[2]);
            g_c2[f] = C[2];
        }
    } else {
        g_c0[f] = make_float4(0.f, 0.f, 1e9f, 0.f);   // padded: inert
        g_c1[f] = make_float4(0.f, 0.f, 0.f, 0.f);
        g_c2[f] = 0.f;
    }

    unsigned bal = __ballot_sync(0xffffffffu, deg);
    if ((tid & 31) == 0) wdeg[tid >> 5] = __popc(bal);
    __syncthreads();
    if (tid == 0) {
        int nd = 0;
        #pragma unroll
        for (int i = 0; i < 8; i++) nd += wdeg[i];
        g_degblk[blockIdx.x] = nd;
    }
}

// ---------------------------------------------------------------------------
// Kernel 2: fused render + combine + reduce. grid (16,16,SPLIT), 256 threads.
// ---------------------------------------------------------------------------
__global__ void __launch_bounds__(256) render_kernel(
    const float* __restrict__ ref,
    float*       __restrict__ out)
{
    __shared__ float4 sA[CHUNK + 2], sB[CHUNK + 2];
    __shared__ float  sC[CHUNK + 2];
    __shared__ int    wcnt[4];
    __shared__ int    s_flag;
    __shared__ float  red[256];

    const int tid  = threadIdx.x;
    const int lane = tid & 31, wid = tid >> 5;
    const int c0 = blockIdx.x * 16, r0 = blockIdx.y * 16;
    const int tileIdx = blockIdx.y * 16 + blockIdx.x;
    const int z = blockIdx.z;

    const float xmin = (2.f * c0 + 1.f)        * (1.f / 256.f) - 1.f;
    const float xmax = (2.f * (c0 + 15) + 1.f) * (1.f / 256.f) - 1.f;
    const float ymax = 1.f - (2.f * r0 + 1.f)        * (1.f / 256.f);
    const float ymin = 1.f - (2.f * (r0 + 15) + 1.f) * (1.f / 256.f);

    // ---------------- Phase A: load coeffs + sum-relu tile cull -------------
    bool keep = false;
    float4 fa = make_float4(0,0,0,0), fb = make_float4(0,0,0,0);
    float  fcc = 0.f;
    if (tid < CHUNK) {
        int f = z * CHUNK + tid;
        fa = g_c0[f]; fb = g_c1[f]; fcc = g_c2[f];
        float m0 = (fa.x > 0.f ? fa.x * xmin : fa.x * xmax)
                 + (fa.y > 0.f ? fa.y * ymin : fa.y * ymax) + fa.z;
        float m1 = (fa.w > 0.f ? fa.w * xmin : fa.w * xmax)
                 + (fb.x > 0.f ? fb.x * ymin : fb.x * ymax) + fb.y;
        float m2 = (fb.z > 0.f ? fb.z * xmin : fb.z * xmax)
                 + (fb.w > 0.f ? fb.w * ymin : fb.w * ymax) + fcc;
        float q = fmaxf(m0, 0.f) + fmaxf(m1, 0.f) + fmaxf(m2, 0.f);
        keep = q < CULL_T;
    }
    unsigned balK = __ballot_sync(0xffffffffu, keep);
    if (lane == 0 && wid < 4) wcnt[wid] = __popc(balK);
    __syncthreads();

    const int cnt = wcnt[0] + wcnt[1] + wcnt[2] + wcnt[3];
    if (keep) {
        int off = __popc(balK & ((1u << lane) - 1u));
        #pragma unroll
        for (int w2 = 0; w2 < 3; w2++) if (w2 < wid) off += wcnt[w2];
        sA[off] = fa; sB[off] = fb; sC[off] = fcc;
    }
    // pad list to a multiple of 3 with inert entries (L=+1e9 -> factor 1 exactly)
    if (tid < 2) {
        sA[cnt + tid] = make_float4(0.f, 0.f, 1e9f, 0.f);
        sB[cnt + tid] = make_float4(0.f, 0.f, 0.f, 0.f);
        sC[cnt + tid] = 0.f;
    }
    __syncthreads();

    const int gc = c0 + (tid & 15);
    const int gr = r0 + (tid >> 4);
    const int pix = gr * IMG + gc;
    const int cntp = ((cnt + 2) / 3) * 3;

    // ---------------- Phase B: branchless 3-way ILP product -----------------
    const float X = (2.f * gc + 1.f) * (1.f / 256.f) - 1.f;
    const float Y = 1.f - (2.f * gr + 1.f) * (1.f / 256.f);
    float pr0 = 1.f, pr1 = 1.f, pr2 = 1.f;
    for (int i = 0; i < cntp; i += 3) {
        float4 a0 = sA[i],     b0 = sB[i];     float c0v = sC[i];
        float4 a1 = sA[i + 1], b1 = sB[i + 1]; float c1v = sC[i + 1];
        float4 a2 = sA[i + 2], b2 = sB[i + 2]; float c2v = sC[i + 2];

        float u00 = 1.f + ex2f(fmaf(a0.x, X, fmaf(a0.y, Y, a0.z)));
        float u01 = 1.f + ex2f(fmaf(a0.w, X, fmaf(b0.x, Y, b0.y)));
        float u02 = 1.f + ex2f(fmaf(b0.z, X, fmaf(b0.w, Y, c0v)));
        float u10 = 1.f + ex2f(fmaf(a1.x, X, fmaf(a1.y, Y, a1.z)));
        float u11 = 1.f + ex2f(fmaf(a1.w, X, fmaf(b1.x, Y, b1.y)));
        float u12 = 1.f + ex2f(fmaf(b1.z, X, fmaf(b1.w, Y, c1v)));
        float u20 = 1.f + ex2f(fmaf(a2.x, X, fmaf(a2.y, Y, a2.z)));
        float u21 = 1.f + ex2f(fmaf(a2.w, X, fmaf(b2.x, Y, b2.y)));
        float u22 = 1.f + ex2f(fmaf(b2.z, X, fmaf(b2.w, Y, c2v)));

        float r0v = rcpaf(u00 * u01 * u02);   // frag (u >= 1 -> no 0*inf)
        float r1v = rcpaf(u10 * u11 * u12);
        float r2v = rcpaf(u20 * u21 * u22);

        pr0 = fmaf(pr0, -r0v, pr0);           // independent chains
        pr1 = fmaf(pr1, -r1v, pr1);
        pr2 = fmaf(pr2, -r2v, pr2);
    }
    g_part[z * (IMG * IMG) + pix] = pr0 * pr1 * pr2;

    // ---------------- Phase C: last chunk per tile combines ------------------
    __syncthreads();                        // all writes done block-wide
    if (tid == 0) {
        __threadfence();                    // release: publish block's g_part plane
        unsigned old = atomicInc(&g_tcnt[tileIdx], SPLIT - 1);  // wraps -> replay-safe
        s_flag = (old == SPLIT - 1);
        if (s_flag) __threadfence();        // acquire: other planes now visible
    }
    __syncthreads();
    if (!s_flag) return;

    float p = 1.f;
    #pragma unroll
    for (int zz = 0; zz < SPLIT; zz++) p *= g_part[zz * (IMG * IMG) + pix];
    // degenerate faces: uniform frag 0.125 -> global factor 0.875^ndeg
    int nd = g_degblk[0] + g_degblk[1] + g_degblk[2] + g_degblk[3];
    for (int i = 0; i < nd; i++) p *= 0.875f;

    float sil = 1.f - p;
    float d = sil - ref[pix];
    red[tid] = d * d;
    __syncthreads();
    #pragma unroll
    for (int s2 = 128; s2 > 0; s2 >>= 1) {
        if (tid < s2) red[tid] += red[tid + s2];
        __syncthreads();
    }

    // ---------------- Phase D: last tile sums 256 tile losses ----------------
    if (tid == 0) {
        g_row[tileIdx] = red[0];
        __threadfence();                    // release tile loss
        unsigned old = atomicInc(&g_done, 255u);  // wraps each replay
        s_flag = (old == 255u);
        if (s_flag) __threadfence();        // acquire all tile losses
    }
    __syncthreads();
    if (!s_flag) return;

    red[tid] = g_row[tid];
    __syncthreads();
    #pragma unroll
    for (int s2 = 128; s2 > 0; s2 >>= 1) {
        if (tid < s2) red[tid] += red[tid + s2];
        __syncthreads();
    }
    if (tid == 0) out[0] = red[0];
}

extern "C" void kernel_launch(void* const* d_in, const int* in_sizes, int n_in,
                              void* d_out, int out_size)
{
    const float* verts = (const float*)d_in[0];   // (1,502,3)
    const int*   faces = (const int*)  d_in[1];   // (1,1000,3)
    const float* cam   = (const float*)d_in[2];   // (3,)
    const float* ref   = (const float*)d_in[3];   // (1,256,256)

    prep_kernel<<<4, 256>>>(verts, faces, cam);

    dim3 grid(IMG / 16, IMG / 16, SPLIT);
    render_kernel<<<grid, 256>>>(ref, (float*)d_out);
}

// round 8
// speedup vs baseline: 1.3348x; 1.0696x over previous
#include <cuda_runtime.h>
#include <cstdint>

#define NFACES 1000
#define NPAD   1024
#define IMG    256
#define SPLIT  16
#define CHUNK  64                 // 16*64 = 1024 faces padded
#define NTILES 256
#define NITEMS (NTILES * SPLIT)   // 4096 work items, tile-major
#define CULL_T 25.5f              // frag < 2^-25.5 -> (1-frag) rounds to exactly 1.0f
#define NBLOCKS 1024

__device__ float4   g_c0[NPAD];               // (A0,B0,C0,A1)
__device__ float4   g_c1[NPAD];               // (B1,C1,A2,B2)
__device__ float    g_c2[NPAD];               // C2
__device__ int      g_degblk[4];              // degenerate counts per prep block
__device__ float    g_part[SPLIT * IMG * IMG];
__device__ float    g_row[NTILES];
__device__ unsigned g_tcnt[NTILES];           // wrapping -> replay-safe
__device__ unsigned g_done;                   // wrapping -> replay-safe
__device__ unsigned g_qhead;                  // work queue head (prep resets)

__device__ __forceinline__ float ex2f(float x) {
    float y; asm("ex2.approx.f32 %0, %1;" : "=f"(y) : "f"(x)); return y;
}
__device__ __forceinline__ float rcpaf(float x) {
    float y; asm("rcp.approx.f32 %0, %1;" : "=f"(y) : "f"(x)); return y;
}
__device__ __forceinline__ float rsqaf(float x) {
    float y; asm("rsqrt.approx.f32 %0, %1;" : "=f"(y) : "f"(x)); return y;
}

// ---------------------------------------------------------------------------
// Kernel 1: per-face prep -> packed edge coefficients + degenerate counts.
// Also resets the work queue for this replay.
// ---------------------------------------------------------------------------
__global__ void __launch_bounds__(256) prep_kernel(
    const float* __restrict__ verts,
    const int*   __restrict__ faces,
    const float* __restrict__ cam)
{
    __shared__ int wdeg[8];
    const int tid = threadIdx.x;
    const int f   = blockIdx.x * 256 + tid;

    if (blockIdx.x == 0 && tid == 0) g_qhead = 0u;   // replay reset

    bool deg = false;

    if (f < NFACES) {
        float ex = cam[0], ey = cam[1], ez = cam[2];

        // camera basis (z = normalize(-eye), up = (0,1,0))
        float rz = rsqaf(ex*ex + ey*ey + ez*ez);
        float zx = -ex * rz, zy = -ey * rz, zz = -ez * rz;
        float rx = rsqaf(zz*zz + zx*zx);
        float xx = zz * rx, xz = -zx * rx;
        float yx = zy * xz;
        float yy = zz * xx - zx * xz;
        float yz = -zy * xx;

        const float w = 0.57735026918962576f;  // tan(30 deg)

        float px[3], py[3];
        #pragma unroll
        for (int k = 0; k < 3; k++) {
            int vi = faces[3 * f + k];
            float dx = verts[3 * vi + 0] - ex;
            float dy = verts[3 * vi + 1] - ey;
            float dz = verts[3 * vi + 2] - ez;
            float cx = xx * dx + xz * dz;            // x.y == 0
            float cy = yx * dx + yy * dy + yz * dz;
            float cz = zx * dx + zy * dy + zz * dz;
            float rzw = rcpaf(cz * w);
            px[k] = cx * rzw;
            py[k] = cy * rzw;
        }

        float e01x = px[1] - px[0], e01y = py[1] - py[0];
        float e02x = px[2] - px[0], e02y = py[2] - py[0];
        float area = __fmul_rn(e01x, e02y) - __fmul_rn(e01y, e02x);

        if (area == 0.f) {
            deg = true;   // duplicate-vertex face: frag = 0.125 everywhere (analytic)
            g_c0[f] = make_float4(0.f, 0.f, 1e9f, 0.f);  // inert
            g_c1[f] = make_float4(0.f, 0.f, 0.f, 0.f);
            g_c2[f] = 0.f;
        } else {
            float s = (area > 0.f) ? 1.f : -1.f;
            float K = s * 144.26950408889634f;  // inv_sigma * log2(e)

            float A[3], B[3], C[3];
            const int ia[3] = {0, 1, 2}, ib[3] = {1, 2, 0};
            #pragma unroll
            for (int e = 0; e < 3; e++) {
                float ax = px[ib[e]] - px[ia[e]];
                float ay = py[ib[e]] - py[ia[e]];
                float rlen = rsqaf(ax*ax + ay*ay);
                float nx = -ay * rlen, ny = ax * rlen;
                A[e] = -K * nx;
                B[e] = -K * ny;
                C[e] =  K * (px[ia[e]] * nx + py[ia[e]] * ny);
            }
            g_c0[f] = make_float4(A[0], B[0], C[0], A[1]);
            g_c1[f] = make_float4(B[1], C[1], A[2], B[2]);
            g_c2[f] = C[2];
        }
    } else {
        g_c0[f] = make_float4(0.f, 0.f, 1e9f, 0.f);   // padded: inert
        g_c1[f] = make_float4(0.f, 0.f, 0.f, 0.f);
        g_c2[f] = 0.f;
    }

    unsigned bal = __ballot_sync(0xffffffffu, deg);
    if ((tid & 31) == 0) wdeg[tid >> 5] = __popc(bal);
    __syncthreads();
    if (tid == 0) {
        int nd = 0;
        #pragma unroll
        for (int i = 0; i < 8; i++) nd += wdeg[i];
        g_degblk[blockIdx.x] = nd;
    }
}

// ---------------------------------------------------------------------------
// Kernel 2: work-stealing render + combine + reduce. NBLOCKS x 256 threads.
// Item = (tile, z); tile-major so a heavy tile's 16 chunks spread across SMs.
// ---------------------------------------------------------------------------
__global__ void __launch_bounds__(256) render_kernel(
    const float* __restrict__ ref,
    float*       __restrict__ out)
{
    __shared__ float4 sA[CHUNK + 2], sB[CHUNK + 2];
    __shared__ float  sC[CHUNK + 2];
    __shared__ int    wcnt[2];
    __shared__ int    s_item;
    __shared__ int    s_flag;
    __shared__ float  red[256];

    const int tid  = threadIdx.x;
    const int lane = tid & 31, wid = tid >> 5;

    for (;;) {
        if (tid == 0) s_item = (int)atomicAdd(&g_qhead, 1u);
        __syncthreads();
        const int item = s_item;
        if (item >= NITEMS) return;

        const int tileIdx = item >> 4;          // tile-major
        const int z       = item & (SPLIT - 1);
        const int c0 = (tileIdx & 15) * 16, r0 = (tileIdx >> 4) * 16;

        const float xmin = (2.f * c0 + 1.f)        * (1.f / 256.f) - 1.f;
        const float xmax = (2.f * (c0 + 15) + 1.f) * (1.f / 256.f) - 1.f;
        const float ymax = 1.f - (2.f * r0 + 1.f)        * (1.f / 256.f);
        const float ymin = 1.f - (2.f * (r0 + 15) + 1.f) * (1.f / 256.f);

        // ---------------- Phase A: load coeffs + sum-relu tile cull ---------
        bool keep = false;
        float4 fa = make_float4(0,0,0,0), fb = make_float4(0,0,0,0);
        float  fcc = 0.f;
        if (tid < CHUNK) {
            int f = z * CHUNK + tid;
            fa = g_c0[f]; fb = g_c1[f]; fcc = g_c2[f];
            float m0 = (fa.x > 0.f ? fa.x * xmin : fa.x * xmax)
                     + (fa.y > 0.f ? fa.y * ymin : fa.y * ymax) + fa.z;
            float m1 = (fa.w > 0.f ? fa.w * xmin : fa.w * xmax)
                     + (fb.x > 0.f ? fb.x * ymin : fb.x * ymax) + fb.y;
            float m2 = (fb.z > 0.f ? fb.z * xmin : fb.z * xmax)
                     + (fb.w > 0.f ? fb.w * ymin : fb.w * ymax) + fcc;
            float q = fmaxf(m0, 0.f) + fmaxf(m1, 0.f) + fmaxf(m2, 0.f);
            keep = q < CULL_T;
        }
        unsigned balK = __ballot_sync(0xffffffffu, keep);
        if (lane == 0 && wid < 2) wcnt[wid] = __popc(balK);
        __syncthreads();

        const int cnt = wcnt[0] + wcnt[1];
        if (keep) {
            int off = __popc(balK & ((1u << lane) - 1u)) + (wid == 1 ? wcnt[0] : 0);
            sA[off] = fa; sB[off] = fb; sC[off] = fcc;
        }
        if (tid < 2) {   // pad to multiple of 3 with inert entries
            sA[cnt + tid] = make_float4(0.f, 0.f, 1e9f, 0.f);
            sB[cnt + tid] = make_float4(0.f, 0.f, 0.f, 0.f);
            sC[cnt + tid] = 0.f;
        }
        __syncthreads();

        const int gc = c0 + (tid & 15);
        const int gr = r0 + (tid >> 4);
        const int pix = gr * IMG + gc;
        const int cntp = ((cnt + 2) / 3) * 3;

        // ---------------- Phase B: branchless 3-way ILP product -------------
        const float X = (2.f * gc + 1.f) * (1.f / 256.f) - 1.f;
        const float Y = 1.f - (2.f * gr + 1.f) * (1.f / 256.f);
        float pr0 = 1.f, pr1 = 1.f, pr2 = 1.f;
        for (int i = 0; i < cntp; i += 3) {
            float4 a0 = sA[i],     b0 = sB[i];     float c0v = sC[i];
            float4 a1 = sA[i + 1], b1 = sB[i + 1]; float c1v = sC[i + 1];
            float4 a2 = sA[i + 2], b2 = sB[i + 2]; float c2v = sC[i + 2];

            float u00 = 1.f + ex2f(fmaf(a0.x, X, fmaf(a0.y, Y, a0.z)));
            float u01 = 1.f + ex2f(fmaf(a0.w, X, fmaf(b0.x, Y, b0.y)));
            float u02 = 1.f + ex2f(fmaf(b0.z, X, fmaf(b0.w, Y, c0v)));
            float u10 = 1.f + ex2f(fmaf(a1.x, X, fmaf(a1.y, Y, a1.z)));
            float u11 = 1.f + ex2f(fmaf(a1.w, X, fmaf(b1.x, Y, b1.y)));
            float u12 = 1.f + ex2f(fmaf(b1.z, X, fmaf(b1.w, Y, c1v)));
            float u20 = 1.f + ex2f(fmaf(a2.x, X, fmaf(a2.y, Y, a2.z)));
            float u21 = 1.f + ex2f(fmaf(a2.w, X, fmaf(b2.x, Y, b2.y)));
            float u22 = 1.f + ex2f(fmaf(b2.z, X, fmaf(b2.w, Y, c2v)));

            float r0v = rcpaf(u00 * u01 * u02);   // frag (u >= 1 -> no 0*inf)
            float r1v = rcpaf(u10 * u11 * u12);
            float r2v = rcpaf(u20 * u21 * u22);

            pr0 = fmaf(pr0, -r0v, pr0);           // independent chains
            pr1 = fmaf(pr1, -r1v, pr1);
            pr2 = fmaf(pr2, -r2v, pr2);
        }
        g_part[z * (IMG * IMG) + pix] = pr0 * pr1 * pr2;

        // ---------------- Phase C: last chunk per tile combines -------------
        __syncthreads();
        if (tid == 0) {
            __threadfence();                    // release this plane
            unsigned old = atomicInc(&g_tcnt[tileIdx], SPLIT - 1);
            s_flag = (old == SPLIT - 1);
            if (s_flag) __threadfence();        // acquire other planes
        }
        __syncthreads();
        if (!s_flag) continue;

        float p = 1.f;
        #pragma unroll
        for (int zz = 0; zz < SPLIT; zz++) p *= g_part[zz * (IMG * IMG) + pix];
        int nd = g_degblk[0] + g_degblk[1] + g_degblk[2] + g_degblk[3];
        for (int i = 0; i < nd; i++) p *= 0.875f;

        float sil = 1.f - p;
        float d = sil - ref[pix];
        red[tid] = d * d;
        __syncthreads();
        #pragma unroll
        for (int s2 = 128; s2 > 0; s2 >>= 1) {
            if (tid < s2) red[tid] += red[tid + s2];
            __syncthreads();
        }

        // ---------------- Phase D: last tile sums all tile losses -----------
        if (tid == 0) {
            g_row[tileIdx] = red[0];
            __threadfence();
            unsigned old = atomicInc(&g_done, NTILES - 1);
            s_flag = (old == NTILES - 1);
            if (s_flag) __threadfence();
        }
        __syncthreads();
        if (!s_flag) continue;

        red[tid] = g_row[tid];
        __syncthreads();
        #pragma unroll
        for (int s2 = 128; s2 > 0; s2 >>= 1) {
            if (tid < s2) red[tid] += red[tid + s2];
            __syncthreads();
        }
        if (tid == 0) out[0] = red[0];
        __syncthreads();
    }
}

extern "C" void kernel_launch(void* const* d_in, const int* in_sizes, int n_in,
                              void* d_out, int out_size)
{
    const float* verts = (const float*)d_in[0];   // (1,502,3)
    const int*   faces = (const int*)  d_in[1];   // (1,1000,3)
    const float* cam   = (const float*)d_in[2];   // (3,)
    const float* ref   = (const float*)d_in[3];   // (1,256,256)

    prep_kernel<<<4, 256>>>(verts, faces, cam);
    render_kernel<<<NBLOCKS, 256>>>(ref, (float*)d_out);
}